// round 5
// baseline (speedup 1.0000x reference)
#include <cuda_runtime.h>
#include <cuda_bf16.h>
#include <math.h>

#define N_NODES 100000
#define N_EDGES 800000
#define D 64
#define D_FEAT 10
#define VOCAB 100
#define EPS 1e-8f

// packed fp32x2 ops (sm_100+; ptxas only emits via explicit PTX)
#define FMA_F32X2(out, a, b, c) \
    asm("fma.rn.f32x2 %0, %1, %2, %3;" : "=l"(out) : "l"(a), "l"(b), "l"(c))
#define ADD_F32X2(out, a, b) \
    asm("add.rn.f32x2 %0, %1, %2;" : "=l"(out) : "l"(a), "l"(b))

// ---------------- static device scratch ----------------
__device__ float g_z[N_NODES * D];      // z1
__device__ float g_h[N_NODES * D];      // hidden activations
__device__ float g_z2[N_NODES * D];     // z2
__device__ int   g_indeg[N_NODES];
__device__ int   g_off[N_NODES + 1];
__device__ int   g_cursor[N_NODES];
__device__ int   g_srcs[N_EDGES];
__device__ float g_nv[VOCAB * D];       // node_emb @ conv1_W^T
__device__ float g_fw2t[D_FEAT * D];    // (conv1_W @ feat_W)^T  [k][d]
__device__ float g_c[D];                // conv1_W @ feat_b

// ---------------- CSR build ----------------
__global__ void count_kernel(const int2* __restrict__ edges) {
    int e = blockIdx.x * blockDim.x + threadIdx.x;
    if (e < N_EDGES) atomicAdd(&g_indeg[edges[e].y], 1);
}

#define SCAN_T 1024
#define SCAN_CHUNK ((N_NODES + SCAN_T - 1) / SCAN_T)  // 98

__global__ void scan_kernel() {
    __shared__ int warp_sums[32];
    int tid  = threadIdx.x;
    int lane = tid & 31;
    int wid  = tid >> 5;

    int start = tid * SCAN_CHUNK;
    int end   = min(start + SCAN_CHUNK, N_NODES);

    int total = 0;
    for (int i = start; i < end; i++) total += g_indeg[i];

    int v = total;
    #pragma unroll
    for (int o = 1; o < 32; o <<= 1) {
        int n = __shfl_up_sync(0xFFFFFFFFu, v, o);
        if (lane >= o) v += n;
    }
    if (lane == 31) warp_sums[wid] = v;
    __syncthreads();
    if (wid == 0) {
        int w = warp_sums[lane];
        #pragma unroll
        for (int o = 1; o < 32; o <<= 1) {
            int n = __shfl_up_sync(0xFFFFFFFFu, w, o);
            if (lane >= o) w += n;
        }
        warp_sums[lane] = w;
    }
    __syncthreads();

    int excl = v - total + (wid > 0 ? warp_sums[wid - 1] : 0);

    int run = excl;
    for (int i = start; i < end; i++) {
        int c = g_indeg[i];
        g_off[i]    = run;
        g_cursor[i] = run;
        run += c;
    }
    if (tid == SCAN_T - 1) g_off[N_NODES] = run;
}

__global__ void place_kernel(const int2* __restrict__ edges) {
    int e = blockIdx.x * blockDim.x + threadIdx.x;
    if (e < N_EDGES) {
        int2 ed = edges[e];
        int slot = atomicAdd(&g_cursor[ed.y], 1);
        g_srcs[slot] = ed.x;
    }
}

// ---------------- precompute folded weights (smem-staged, parallel) ----------------
// grid = 26 blocks x 256 threads. Block 0: fw2t + c. Blocks 1..25: 4 vocab rows each.
#define WP 65  // smem pitch (bank-conflict-free for stride-64 access)
__global__ __launch_bounds__(256)
void precompute_kernel(const float* __restrict__ node_emb,
                       const float* __restrict__ feat_W,
                       const float* __restrict__ feat_b,
                       const float* __restrict__ W) {
    __shared__ float sW[D * WP];
    int tid = threadIdx.x;

    // stage W coalesced: W[d][j] -> sW[d*WP + j]
    for (int i = tid; i < D * D; i += 256) sW[(i >> 6) * WP + (i & 63)] = W[i];

    if (blockIdx.x == 0) {
        __shared__ float sFW[D * D_FEAT];
        __shared__ float sFB[D];
        for (int i = tid; i < D * D_FEAT; i += 256) sFW[i] = feat_W[i];
        if (tid < D) sFB[tid] = feat_b[tid];
        __syncthreads();
        // 256 threads: (k, d) pairs; 64*10 = 640 outputs
        for (int i = tid; i < D_FEAT * D; i += 256) {
            int k = i / D, d = i % D;
            float s = 0.f;
            #pragma unroll
            for (int j = 0; j < D; j++) s += sW[d * WP + j] * sFW[j * D_FEAT + k];
            g_fw2t[k * D + d] = s;
        }
        if (tid < D) {
            float cb = 0.f;
            #pragma unroll
            for (int j = 0; j < D; j++) cb += sW[tid * WP + j] * sFB[j];
            g_c[tid] = cb;
        }
    } else {
        __shared__ float sE[4][D];
        int v0 = (blockIdx.x - 1) * 4;
        if (tid < 4 * D) sE[tid >> 6][tid & 63] = node_emb[v0 * D + tid];
        __syncthreads();
        int vl = tid >> 6;      // 0..3
        int d  = tid & 63;
        float s = 0.f;
        #pragma unroll
        for (int j = 0; j < D; j++) s += sW[d * WP + j] * sE[vl][j];
        g_nv[(v0 + vl) * D + d] = s;
    }
}

// ---------------- z1 = nv[nodes] + features @ fw2^T + c ----------------
__global__ __launch_bounds__(256)
void z1_kernel(const int* __restrict__ nodes, const float* __restrict__ features) {
    __shared__ float s_fw2t[D_FEAT * D];
    __shared__ float s_c[D];
    int tid = threadIdx.x;
    for (int i = tid; i < D_FEAT * D; i += 256) s_fw2t[i] = g_fw2t[i];
    if (tid < D) s_c[tid] = g_c[tid];
    __syncthreads();

    int q    = blockIdx.x * 256 + tid;
    int node = q >> 4;
    int dq   = (q & 15) * 4;

    int tok = __ldg(&nodes[node]);
    const float* f = features + node * D_FEAT;
    float fk[D_FEAT];
    #pragma unroll
    for (int k = 0; k < D_FEAT; k++) fk[k] = f[k];

    float4 acc = *(const float4*)&g_nv[tok * D + dq];
    float4 cc  = *(const float4*)&s_c[dq];
    acc.x += cc.x; acc.y += cc.y; acc.z += cc.z; acc.w += cc.w;

    #pragma unroll
    for (int k = 0; k < D_FEAT; k++) {
        float4 w4 = *(const float4*)&s_fw2t[k * D + dq];
        acc.x += fk[k] * w4.x; acc.y += fk[k] * w4.y;
        acc.z += fk[k] * w4.z; acc.w += fk[k] * w4.w;
    }
    *(float4*)&g_z[node * D + dq] = acc;
}

// ---------------- MLP-8 warp aggregation helper ----------------
__device__ __forceinline__ float2 agg_node(const float* __restrict__ z,
                                           int node, int lane) {
    unsigned long long acc =
        *(const unsigned long long*)&z[node * D + lane * 2];
    int s0 = __ldg(&g_off[node]);
    int s1 = __ldg(&g_off[node + 1]);

    for (int base = s0; base < s1; base += 8) {
        int t  = base + (lane & 7);
        int my = (t < s1) ? __ldg(&g_srcs[t]) : 0;
        int cnt = s1 - base;

        unsigned long long v[8];
        #pragma unroll
        for (int k = 0; k < 8; k++) {
            int a = __shfl_sync(0xFFFFFFFFu, my, k);
            v[k] = (k < cnt)
                 ? *(const unsigned long long*)&z[a * D + lane * 2]
                 : 0ULL;
        }
        #pragma unroll
        for (int k = 0; k < 8; k++) ADD_F32X2(acc, acc, v[k]);
    }
    float2 r;
    asm("mov.b64 {%0, %1}, %2;" : "=f"(r.x), "=f"(r.y) : "l"(acc));
    return r;
}

// ---------------- agg + bias + relu: h = relu(z + A z + b) ----------------
__global__ __launch_bounds__(256)
void agg_relu_kernel(const float* __restrict__ z, float* __restrict__ h,
                     const float* __restrict__ bvec) {
    int node = blockIdx.x * 8 + (threadIdx.x >> 5);
    int lane = threadIdx.x & 31;

    float2 acc = agg_node(z, node, lane);
    float2 b2 = *(const float2*)&bvec[lane * 2];
    acc.x = fmaxf(acc.x + b2.x, 0.f);
    acc.y = fmaxf(acc.y + b2.y, 0.f);
    *(float2*)&h[node * D + lane * 2] = acc;
}

// ---------------- GEMM: z2 = h @ W^T (packed f32x2 FMA) ----------------
#define GEMM_GRID 500
__global__ __launch_bounds__(256, 2)
void gemm_kernel(const float* __restrict__ in, float* __restrict__ out,
                 const float* __restrict__ W) {
    __shared__ __align__(16) float xs[8][D];
    int tid = threadIdx.x;
    int sub = tid >> 6;
    int t   = tid & 63;

    unsigned long long w2[32];
    const unsigned long long* Wp = (const unsigned long long*)(W + t * D);
    #pragma unroll
    for (int k = 0; k < 32; k++) w2[k] = Wp[k];

    for (int base = blockIdx.x * 8; base < N_NODES; base += GEMM_GRID * 8) {
        #pragma unroll
        for (int i = tid; i < 8 * D; i += 256) xs[i >> 6][i & 63] = in[base * D + i];
        __syncthreads();

        #pragma unroll
        for (int r = 0; r < 2; r++) {
            int n = sub * 2 + r;
            const unsigned long long* x = (const unsigned long long*)xs[n];
            unsigned long long a0 = 0ULL, a1 = 0ULL;
            #pragma unroll
            for (int d = 0; d < 32; d += 2) {
                FMA_F32X2(a0, x[d],     w2[d],     a0);
                FMA_F32X2(a1, x[d + 1], w2[d + 1], a1);
            }
            float ax, ay, bx, by;
            asm("mov.b64 {%0, %1}, %2;" : "=f"(ax), "=f"(ay) : "l"(a0));
            asm("mov.b64 {%0, %1}, %2;" : "=f"(bx), "=f"(by) : "l"(a1));
            out[(base + n) * D + t] = (ax + ay) + (bx + by);
        }
        __syncthreads();
    }
}

// ---------------- fused final: agg + bias + relu + cosine ----------------
__global__ __launch_bounds__(256)
void agg_cos_kernel(const float* __restrict__ z,
                    const float* __restrict__ bvec,
                    const float* __restrict__ pattern_emb,
                    const int* __restrict__ pid,
                    float* __restrict__ out) {
    int node = blockIdx.x * 8 + (threadIdx.x >> 5);
    int lane = threadIdx.x & 31;

    float2 acc = agg_node(z, node, lane);
    float2 b2 = *(const float2*)&bvec[lane * 2];
    acc.x = fmaxf(acc.x + b2.x, 0.f);
    acc.y = fmaxf(acc.y + b2.y, 0.f);

    int p_id = __ldg(pid);
    float2 pv = *(const float2*)&pattern_emb[p_id * D + lane * 2];

    float num = acc.x * pv.x + acc.y * pv.y;
    float sq  = acc.x * acc.x + acc.y * acc.y;
    float psq = pv.x * pv.x + pv.y * pv.y;

    #pragma unroll
    for (int o = 16; o > 0; o >>= 1) {
        num += __shfl_xor_sync(0xFFFFFFFFu, num, o);
        sq  += __shfl_xor_sync(0xFFFFFFFFu, sq, o);
        psq += __shfl_xor_sync(0xFFFFFFFFu, psq, o);
    }
    if (lane == 0) {
        float denom = fmaxf(sqrtf(sq), EPS) * fmaxf(sqrtf(psq), EPS);
        out[node] = num / denom;
    }
}

// ---------------- launch ----------------
extern "C" void kernel_launch(void* const* d_in, const int* in_sizes, int n_in,
                              void* d_out, int out_size) {
    const int*   nodes       = (const int*)d_in[0];
    const int2*  edges       = (const int2*)d_in[1];
    const float* features    = (const float*)d_in[2];
    const float* node_emb    = (const float*)d_in[3];
    const float* feat_W      = (const float*)d_in[4];
    const float* feat_b      = (const float*)d_in[5];
    const float* conv1_W     = (const float*)d_in[6];
    const float* conv1_b     = (const float*)d_in[7];
    const float* pattern_emb = (const float*)d_in[8];
    const int*   pattern_id  = (const int*)d_in[9];
    float*       out         = (float*)d_out;

    float* z; float* h; float* z2; int* indeg;
    cudaGetSymbolAddress((void**)&z,     g_z);
    cudaGetSymbolAddress((void**)&h,     g_h);
    cudaGetSymbolAddress((void**)&z2,    g_z2);
    cudaGetSymbolAddress((void**)&indeg, g_indeg);

    // CSR build
    cudaMemsetAsync(indeg, 0, N_NODES * sizeof(int));
    count_kernel<<<(N_EDGES + 255) / 256, 256>>>(edges);
    scan_kernel<<<1, SCAN_T>>>();
    place_kernel<<<(N_EDGES + 255) / 256, 256>>>(edges);

    // folded weights + z1
    precompute_kernel<<<VOCAB / 4 + 1, 256>>>(node_emb, feat_W, feat_b, conv1_W);
    z1_kernel<<<(N_NODES * 16) / 256, 256>>>(nodes, features);

    // layer 1: h = relu(z + A z + b)
    agg_relu_kernel<<<N_NODES / 8, 256>>>(z, h, conv1_b);

    // layer 2 linear
    gemm_kernel<<<GEMM_GRID, 256>>>(h, z2, conv1_W);

    // layer 2 agg + relu + cosine
    agg_cos_kernel<<<N_NODES / 8, 256>>>(z2, conv1_b, pattern_emb, pattern_id, out);
}

// round 6
// speedup vs baseline: 1.9351x; 1.9351x over previous
#include <cuda_runtime.h>
#include <cuda_bf16.h>
#include <math.h>

#define N_NODES 100000
#define N_EDGES 800000
#define D 64
#define D_FEAT 10
#define VOCAB 100
#define EPS 1e-8f

#define NB 148     // persistent CSR blocks (<= SM count, all resident)
#define BT 256
#define CHUNK 676  // ceil(N_NODES / NB); 148*676 = 100048 >= 100000

// packed fp32x2 FMA (sm_100+; ptxas only emits via explicit PTX)
#define FMA_F32X2(out, a, b, c) \
    asm("fma.rn.f32x2 %0, %1, %2, %3;" : "=l"(out) : "l"(a), "l"(b), "l"(c))

// ---------------- static device scratch ----------------
__device__ float g_z[N_NODES * D];
__device__ float g_h[N_NODES * D];
__device__ float g_z2[N_NODES * D];
__device__ int   g_indeg[N_NODES];
__device__ int   g_off[N_NODES + 1];
__device__ int   g_cursor[N_NODES];
__device__ int   g_srcs[N_EDGES];
__device__ float g_nv[VOCAB * D];
__device__ float g_fw2t[D_FEAT * D];
__device__ float g_c[D];
__device__ unsigned int g_barrier[8];   // zero-init; atomicInc wraps back to 0 each replay
__device__ int g_bsum[NB];
__device__ int g_bbase[NB];

// ---------------- grid barrier (self-resetting via atomicInc wrap) ----------------
__device__ __forceinline__ void gbar(int i) {
    __syncthreads();
    if (threadIdx.x == 0) {
        __threadfence();
        atomicInc(&g_barrier[i], NB - 1u);          // 148th increment wraps to 0
        volatile unsigned int* p = &g_barrier[i];
        while (*p != 0u) __nanosleep(32);
        __threadfence();
    }
    __syncthreads();
}

// ---------------- single-kernel CSR build ----------------
__global__ __launch_bounds__(BT)
void csr_build_kernel(const int2* __restrict__ edges) {
    int tid  = threadIdx.x;
    int b    = blockIdx.x;
    int lane = tid & 31;
    int w    = tid >> 5;
    int gt   = b * BT + tid;
    const int gs = NB * BT;

    __shared__ int sm8[8];

    // phase 1: zero indeg (coalesced)
    for (int i = gt; i < N_NODES; i += gs) g_indeg[i] = 0;
    gbar(0);

    // phase 2: count
    for (int e = gt; e < N_EDGES; e += gs) atomicAdd(&g_indeg[edges[e].y], 1);
    gbar(1);

    // phase 3: per-block partial sum over contiguous chunk (coalesced)
    int cs = b * CHUNK;
    int ce = min(cs + CHUNK, N_NODES);
    {
        int s = 0;
        for (int i = cs + tid; i < ce; i += BT) s += g_indeg[i];
        #pragma unroll
        for (int o = 16; o; o >>= 1) s += __shfl_xor_sync(0xFFFFFFFFu, s, o);
        if (lane == 0) sm8[w] = s;
        __syncthreads();
        if (tid == 0) {
            int t = 0;
            #pragma unroll
            for (int k = 0; k < 8; k++) t += sm8[k];
            g_bsum[b] = t;
        }
    }
    gbar(2);

    // phase 4: block 0 exclusive-scans the 148 block sums
    if (b == 0) {
        int x = (tid < NB) ? g_bsum[tid] : 0;
        int incl = x;
        #pragma unroll
        for (int o = 1; o < 32; o <<= 1) {
            int n = __shfl_up_sync(0xFFFFFFFFu, incl, o);
            if (lane >= o) incl += n;
        }
        __syncthreads();               // sm8 reuse guard
        if (lane == 31) sm8[w] = incl;
        __syncthreads();
        if (w == 0 && lane < 8) {
            int v = sm8[lane];
            #pragma unroll
            for (int o = 1; o < 8; o <<= 1) {
                int n = __shfl_up_sync(0xFFu, v, o);
                if (lane >= o) v += n;
            }
            sm8[lane] = v;
        }
        __syncthreads();
        int excl = incl - x + (w ? sm8[w - 1] : 0);
        if (tid < NB) g_bbase[tid] = excl;
    }
    gbar(3);

    // phase 5: per-block coalesced tile scans -> off, cursor
    {
        int run = g_bbase[b];
        for (int t0 = cs; t0 < cs + CHUNK; t0 += BT) {
            int i = t0 + tid;
            int x = (i < ce) ? g_indeg[i] : 0;
            int incl = x;
            #pragma unroll
            for (int o = 1; o < 32; o <<= 1) {
                int n = __shfl_up_sync(0xFFFFFFFFu, incl, o);
                if (lane >= o) incl += n;
            }
            __syncthreads();           // sm8 reuse guard
            if (lane == 31) sm8[w] = incl;
            __syncthreads();
            if (w == 0 && lane < 8) {
                int v = sm8[lane];
                #pragma unroll
                for (int o = 1; o < 8; o <<= 1) {
                    int n = __shfl_up_sync(0xFFu, v, o);
                    if (lane >= o) v += n;
                }
                sm8[lane] = v;
            }
            __syncthreads();
            int excl = incl - x + (w ? sm8[w - 1] : 0) + run;
            if (i < ce) { g_off[i] = excl; g_cursor[i] = excl; }
            run += sm8[7];             // tile total (read before next overwrite)
        }
        if (b == 0 && tid == 0) g_off[N_NODES] = N_EDGES;
    }
    gbar(4);

    // phase 6: place
    for (int e = gt; e < N_EDGES; e += gs) {
        int2 ed = edges[e];
        int slot = atomicAdd(&g_cursor[ed.y], 1);
        g_srcs[slot] = ed.x;
    }
}

// ---------------- precompute folded weights ----------------
#define WP 65
__global__ __launch_bounds__(256)
void precompute_kernel(const float* __restrict__ node_emb,
                       const float* __restrict__ feat_W,
                       const float* __restrict__ feat_b,
                       const float* __restrict__ W) {
    __shared__ float sW[D * WP];
    int tid = threadIdx.x;
    for (int i = tid; i < D * D; i += 256) sW[(i >> 6) * WP + (i & 63)] = W[i];

    if (blockIdx.x == 0) {
        __shared__ float sFW[D * D_FEAT];
        __shared__ float sFB[D];
        for (int i = tid; i < D * D_FEAT; i += 256) sFW[i] = feat_W[i];
        if (tid < D) sFB[tid] = feat_b[tid];
        __syncthreads();
        for (int i = tid; i < D_FEAT * D; i += 256) {
            int k = i / D, d = i % D;
            float s = 0.f;
            #pragma unroll
            for (int j = 0; j < D; j++) s += sW[d * WP + j] * sFW[j * D_FEAT + k];
            g_fw2t[k * D + d] = s;
        }
        if (tid < D) {
            float cb = 0.f;
            #pragma unroll
            for (int j = 0; j < D; j++) cb += sW[tid * WP + j] * sFB[j];
            g_c[tid] = cb;
        }
    } else {
        __shared__ float sE[4][D];
        int v0 = (blockIdx.x - 1) * 4;
        if (tid < 4 * D) sE[tid >> 6][tid & 63] = node_emb[v0 * D + tid];
        __syncthreads();
        int vl = tid >> 6;
        int d  = tid & 63;
        float s = 0.f;
        #pragma unroll
        for (int j = 0; j < D; j++) s += sW[d * WP + j] * sE[vl][j];
        g_nv[(v0 + vl) * D + d] = s;
    }
}

// ---------------- z1 = nv[nodes] + features @ fw2^T + c ----------------
__global__ __launch_bounds__(256)
void z1_kernel(const int* __restrict__ nodes, const float* __restrict__ features) {
    __shared__ float s_fw2t[D_FEAT * D];
    __shared__ float s_c[D];
    int tid = threadIdx.x;
    for (int i = tid; i < D_FEAT * D; i += 256) s_fw2t[i] = g_fw2t[i];
    if (tid < D) s_c[tid] = g_c[tid];
    __syncthreads();

    int q    = blockIdx.x * 256 + tid;
    int node = q >> 4;
    int dq   = (q & 15) * 4;

    int tok = __ldg(&nodes[node]);
    const float* f = features + node * D_FEAT;
    float fk[D_FEAT];
    #pragma unroll
    for (int k = 0; k < D_FEAT; k++) fk[k] = f[k];

    float4 acc = *(const float4*)&g_nv[tok * D + dq];
    float4 cc  = *(const float4*)&s_c[dq];
    acc.x += cc.x; acc.y += cc.y; acc.z += cc.z; acc.w += cc.w;

    #pragma unroll
    for (int k = 0; k < D_FEAT; k++) {
        float4 w4 = *(const float4*)&s_fw2t[k * D + dq];
        acc.x += fk[k] * w4.x; acc.y += fk[k] * w4.y;
        acc.z += fk[k] * w4.z; acc.w += fk[k] * w4.w;
    }
    *(float4*)&g_z[node * D + dq] = acc;
}

// ---------------- simple warp aggregation (R3 style) ----------------
__device__ __forceinline__ float2 agg_node(const float* __restrict__ z,
                                           int node, int lane) {
    float2 acc = *(const float2*)&z[node * D + lane * 2];
    int s0 = __ldg(&g_off[node]);
    int s1 = __ldg(&g_off[node + 1]);

    for (int base = s0; base < s1; base += 32) {
        int cnt = min(32, s1 - base);
        int idx = (base + lane < s1) ? __ldg(&g_srcs[base + lane]) : 0;
        for (int k = 0; k < cnt; k++) {
            int a = __shfl_sync(0xFFFFFFFFu, idx, k);
            float2 v = *(const float2*)&z[a * D + lane * 2];
            acc.x += v.x; acc.y += v.y;
        }
    }
    return acc;
}

// ---------------- agg + bias + relu ----------------
__global__ __launch_bounds__(256)
void agg_relu_kernel(const float* __restrict__ z, float* __restrict__ h,
                     const float* __restrict__ bvec) {
    int node = blockIdx.x * 8 + (threadIdx.x >> 5);
    int lane = threadIdx.x & 31;

    float2 acc = agg_node(z, node, lane);
    float2 b2 = *(const float2*)&bvec[lane * 2];
    acc.x = fmaxf(acc.x + b2.x, 0.f);
    acc.y = fmaxf(acc.y + b2.y, 0.f);
    *(float2*)&h[node * D + lane * 2] = acc;
}

// ---------------- GEMM: z2 = h @ W^T (packed f32x2 FMA) ----------------
#define GEMM_GRID 500
__global__ __launch_bounds__(256, 2)
void gemm_kernel(const float* __restrict__ in, float* __restrict__ out,
                 const float* __restrict__ W) {
    __shared__ __align__(16) float xs[8][D];
    int tid = threadIdx.x;
    int sub = tid >> 6;
    int t   = tid & 63;

    unsigned long long w2[32];
    const unsigned long long* Wp = (const unsigned long long*)(W + t * D);
    #pragma unroll
    for (int k = 0; k < 32; k++) w2[k] = Wp[k];

    for (int base = blockIdx.x * 8; base < N_NODES; base += GEMM_GRID * 8) {
        #pragma unroll
        for (int i = tid; i < 8 * D; i += 256) xs[i >> 6][i & 63] = in[base * D + i];
        __syncthreads();

        #pragma unroll
        for (int r = 0; r < 2; r++) {
            int n = sub * 2 + r;
            const unsigned long long* x = (const unsigned long long*)xs[n];
            unsigned long long a0 = 0ULL, a1 = 0ULL;
            #pragma unroll
            for (int d = 0; d < 32; d += 2) {
                FMA_F32X2(a0, x[d],     w2[d],     a0);
                FMA_F32X2(a1, x[d + 1], w2[d + 1], a1);
            }
            float ax, ay, bx, by;
            asm("mov.b64 {%0, %1}, %2;" : "=f"(ax), "=f"(ay) : "l"(a0));
            asm("mov.b64 {%0, %1}, %2;" : "=f"(bx), "=f"(by) : "l"(a1));
            out[(base + n) * D + t] = (ax + ay) + (bx + by);
        }
        __syncthreads();
    }
}

// ---------------- fused final: agg + bias + relu + cosine ----------------
__global__ __launch_bounds__(256)
void agg_cos_kernel(const float* __restrict__ z,
                    const float* __restrict__ bvec,
                    const float* __restrict__ pattern_emb,
                    const int* __restrict__ pid,
                    float* __restrict__ out) {
    int node = blockIdx.x * 8 + (threadIdx.x >> 5);
    int lane = threadIdx.x & 31;

    float2 acc = agg_node(z, node, lane);
    float2 b2 = *(const float2*)&bvec[lane * 2];
    acc.x = fmaxf(acc.x + b2.x, 0.f);
    acc.y = fmaxf(acc.y + b2.y, 0.f);

    int p_id = __ldg(pid);
    float2 pv = *(const float2*)&pattern_emb[p_id * D + lane * 2];

    float num = acc.x * pv.x + acc.y * pv.y;
    float sq  = acc.x * acc.x + acc.y * acc.y;
    float psq = pv.x * pv.x + pv.y * pv.y;

    #pragma unroll
    for (int o = 16; o > 0; o >>= 1) {
        num += __shfl_xor_sync(0xFFFFFFFFu, num, o);
        sq  += __shfl_xor_sync(0xFFFFFFFFu, sq, o);
        psq += __shfl_xor_sync(0xFFFFFFFFu, psq, o);
    }
    if (lane == 0) {
        float denom = fmaxf(sqrtf(sq), EPS) * fmaxf(sqrtf(psq), EPS);
        out[node] = num / denom;
    }
}

// ---------------- launch ----------------
extern "C" void kernel_launch(void* const* d_in, const int* in_sizes, int n_in,
                              void* d_out, int out_size) {
    const int*   nodes       = (const int*)d_in[0];
    const int2*  edges       = (const int2*)d_in[1];
    const float* features    = (const float*)d_in[2];
    const float* node_emb    = (const float*)d_in[3];
    const float* feat_W      = (const float*)d_in[4];
    const float* feat_b      = (const float*)d_in[5];
    const float* conv1_W     = (const float*)d_in[6];
    const float* conv1_b     = (const float*)d_in[7];
    const float* pattern_emb = (const float*)d_in[8];
    const int*   pattern_id  = (const int*)d_in[9];
    float*       out         = (float*)d_out;

    float* z; float* h; float* z2;
    cudaGetSymbolAddress((void**)&z,  g_z);
    cudaGetSymbolAddress((void**)&h,  g_h);
    cudaGetSymbolAddress((void**)&z2, g_z2);

    // 1: folded weights   2: z1   3: CSR (single persistent kernel)
    precompute_kernel<<<VOCAB / 4 + 1, 256>>>(node_emb, feat_W, feat_b, conv1_W);
    z1_kernel<<<(N_NODES * 16) / 256, 256>>>(nodes, features);
    csr_build_kernel<<<NB, BT>>>(edges);

    // 4: layer-1 agg (ncu sampling lands here)   5: GEMM   6: agg+cosine
    agg_relu_kernel<<<N_NODES / 8, 256>>>(z, h, conv1_b);
    gemm_kernel<<<GEMM_GRID, 256>>>(h, z2, conv1_W);
    agg_cos_kernel<<<N_NODES / 8, 256>>>(z2, conv1_b, pattern_emb, pattern_id, out);
}

// round 7
// speedup vs baseline: 1.9929x; 1.0299x over previous
#include <cuda_runtime.h>
#include <cuda_bf16.h>
#include <math.h>

#define N_NODES 100000
#define N_EDGES 800000
#define D 64
#define D_FEAT 10
#define VOCAB 100
#define EPS 1e-8f

#define NB 148     // persistent CSR blocks
#define BT 256
#define CHUNK 676  // ceil(N_NODES / NB)

// packed fp32x2 ops (sm_100+; ptxas only emits via explicit PTX)
#define FMA_F32X2(out, a, b, c) \
    asm("fma.rn.f32x2 %0, %1, %2, %3;" : "=l"(out) : "l"(a), "l"(b), "l"(c))
#define ADD_F32X2(out, a, b) \
    asm("add.rn.f32x2 %0, %1, %2;" : "=l"(out) : "l"(a), "l"(b))

// ---------------- static device scratch ----------------
__device__ float g_z[N_NODES * D];
__device__ float g_h[N_NODES * D];
__device__ float g_z2[N_NODES * D];
__device__ int   g_indeg[N_NODES];
__device__ int   g_off[N_NODES + 1];
__device__ int   g_cursor[N_NODES];
__device__ int   g_srcs[N_EDGES];
__device__ float g_nv[VOCAB * D];
__device__ float g_fw2t[D_FEAT * D];
__device__ float g_c[D];
__device__ unsigned int g_barrier[8];   // zero-init; atomicInc wraps to 0 each replay
__device__ int g_bsum[NB];
__device__ int g_bbase[NB];

// ---------------- grid barrier (self-resetting) ----------------
__device__ __forceinline__ void gbar(int i) {
    __syncthreads();
    if (threadIdx.x == 0) {
        __threadfence();
        atomicInc(&g_barrier[i], NB - 1u);
        volatile unsigned int* p = &g_barrier[i];
        while (*p != 0u) __nanosleep(32);
        __threadfence();
    }
    __syncthreads();
}

// ---------------- CSR build + folded-weight precompute (one persistent kernel) ----------------
#define WP 65
__global__ __launch_bounds__(BT)
void csr_build_kernel(const int2* __restrict__ edges,
                      const float* __restrict__ node_emb,
                      const float* __restrict__ feat_W,
                      const float* __restrict__ feat_b,
                      const float* __restrict__ W) {
    int tid  = threadIdx.x;
    int b    = blockIdx.x;
    int lane = tid & 31;
    int w    = tid >> 5;
    int gt   = b * BT + tid;
    const int gs = NB * BT;

    __shared__ int sm8[8];

    // phase 0: blocks 0..25 compute folded weights (read only by later z1 kernel;
    // kernel boundary orders it — no grid barrier needed)
    if (b <= 25) {
        __shared__ float sW[D * WP];
        for (int i = tid; i < D * D; i += BT) sW[(i >> 6) * WP + (i & 63)] = W[i];
        if (b == 0) {
            __shared__ float sFW[D * D_FEAT];
            __shared__ float sFB[D];
            for (int i = tid; i < D * D_FEAT; i += BT) sFW[i] = feat_W[i];
            if (tid < D) sFB[tid] = feat_b[tid];
            __syncthreads();
            for (int i = tid; i < D_FEAT * D; i += BT) {
                int k = i / D, d = i % D;
                float s = 0.f;
                #pragma unroll
                for (int j = 0; j < D; j++) s += sW[d * WP + j] * sFW[j * D_FEAT + k];
                g_fw2t[k * D + d] = s;
            }
            if (tid < D) {
                float cb = 0.f;
                #pragma unroll
                for (int j = 0; j < D; j++) cb += sW[tid * WP + j] * sFB[j];
                g_c[tid] = cb;
            }
        } else {
            __shared__ float sE[4][D];
            int v0 = (b - 1) * 4;
            if (tid < 4 * D) sE[tid >> 6][tid & 63] = node_emb[v0 * D + tid];
            __syncthreads();
            int vl = tid >> 6;
            int d  = tid & 63;
            float s = 0.f;
            #pragma unroll
            for (int j = 0; j < D; j++) s += sW[d * WP + j] * sE[vl][j];
            g_nv[(v0 + vl) * D + d] = s;
        }
        __syncthreads();
    }

    // phase 1: zero indeg
    for (int i = gt; i < N_NODES; i += gs) g_indeg[i] = 0;
    gbar(0);

    // phase 2: count
    for (int e = gt; e < N_EDGES; e += gs) atomicAdd(&g_indeg[edges[e].y], 1);
    gbar(1);

    // phase 3: per-block partial sums
    int cs = b * CHUNK;
    int ce = min(cs + CHUNK, N_NODES);
    {
        int s = 0;
        for (int i = cs + tid; i < ce; i += BT) s += g_indeg[i];
        #pragma unroll
        for (int o = 16; o; o >>= 1) s += __shfl_xor_sync(0xFFFFFFFFu, s, o);
        if (lane == 0) sm8[w] = s;
        __syncthreads();
        if (tid == 0) {
            int t = 0;
            #pragma unroll
            for (int k = 0; k < 8; k++) t += sm8[k];
            g_bsum[b] = t;
        }
    }
    gbar(2);

    // phase 4: block 0 scans block sums
    if (b == 0) {
        int x = (tid < NB) ? g_bsum[tid] : 0;
        int incl = x;
        #pragma unroll
        for (int o = 1; o < 32; o <<= 1) {
            int n = __shfl_up_sync(0xFFFFFFFFu, incl, o);
            if (lane >= o) incl += n;
        }
        __syncthreads();
        if (lane == 31) sm8[w] = incl;
        __syncthreads();
        if (w == 0 && lane < 8) {
            int v = sm8[lane];
            #pragma unroll
            for (int o = 1; o < 8; o <<= 1) {
                int n = __shfl_up_sync(0xFFu, v, o);
                if (lane >= o) v += n;
            }
            sm8[lane] = v;
        }
        __syncthreads();
        int excl = incl - x + (w ? sm8[w - 1] : 0);
        if (tid < NB) g_bbase[tid] = excl;
    }
    gbar(3);

    // phase 5: per-block tile scans -> off, cursor
    {
        int run = g_bbase[b];
        for (int t0 = cs; t0 < cs + CHUNK; t0 += BT) {
            int i = t0 + tid;
            int x = (i < ce) ? g_indeg[i] : 0;
            int incl = x;
            #pragma unroll
            for (int o = 1; o < 32; o <<= 1) {
                int n = __shfl_up_sync(0xFFFFFFFFu, incl, o);
                if (lane >= o) incl += n;
            }
            __syncthreads();
            if (lane == 31) sm8[w] = incl;
            __syncthreads();
            if (w == 0 && lane < 8) {
                int v = sm8[lane];
                #pragma unroll
                for (int o = 1; o < 8; o <<= 1) {
                    int n = __shfl_up_sync(0xFFu, v, o);
                    if (lane >= o) v += n;
                }
                sm8[lane] = v;
            }
            __syncthreads();
            int excl = incl - x + (w ? sm8[w - 1] : 0) + run;
            if (i < ce) { g_off[i] = excl; g_cursor[i] = excl; }
            run += sm8[7];
        }
        if (b == 0 && tid == 0) g_off[N_NODES] = N_EDGES;
    }
    gbar(4);

    // phase 6: place
    for (int e = gt; e < N_EDGES; e += gs) {
        int2 ed = edges[e];
        int slot = atomicAdd(&g_cursor[ed.y], 1);
        g_srcs[slot] = ed.x;
    }
}

// ---------------- z1 = nv[nodes] + features @ fw2^T + c ----------------
__global__ __launch_bounds__(256)
void z1_kernel(const int* __restrict__ nodes, const float* __restrict__ features) {
    __shared__ float s_fw2t[D_FEAT * D];
    __shared__ float s_c[D];
    int tid = threadIdx.x;
    for (int i = tid; i < D_FEAT * D; i += 256) s_fw2t[i] = g_fw2t[i];
    if (tid < D) s_c[tid] = g_c[tid];
    __syncthreads();

    int q    = blockIdx.x * 256 + tid;
    int node = q >> 4;
    int dq   = (q & 15) * 4;

    int tok = __ldg(&nodes[node]);
    const float* f = features + node * D_FEAT;
    float fk[D_FEAT];
    #pragma unroll
    for (int k = 0; k < D_FEAT; k++) fk[k] = f[k];

    float4 acc = *(const float4*)&g_nv[tok * D + dq];
    float4 cc  = *(const float4*)&s_c[dq];
    acc.x += cc.x; acc.y += cc.y; acc.z += cc.z; acc.w += cc.w;

    #pragma unroll
    for (int k = 0; k < D_FEAT; k++) {
        float4 w4 = *(const float4*)&s_fw2t[k * D + dq];
        acc.x += fk[k] * w4.x; acc.y += fk[k] * w4.y;
        acc.z += fk[k] * w4.z; acc.w += fk[k] * w4.w;
    }
    *(float4*)&g_z[node * D + dq] = acc;
}

// ---------------- aggregation: shfl-free, 8 independent idx->row chains ----------------
__device__ __forceinline__ float2 agg_node(const float* __restrict__ z,
                                           int node, int lane) {
    unsigned long long acc0 =
        *(const unsigned long long*)&z[node * D + lane * 2];
    unsigned long long acc1 = 0ULL;
    int s0 = __ldg(&g_off[node]);
    int s1 = __ldg(&g_off[node + 1]);

    for (int j = s0; j < s1; j += 8) {
        unsigned long long v[8];
        #pragma unroll
        for (int k = 0; k < 8; k++) {
            if (j + k < s1) {
                int a = __ldg(&g_srcs[j + k]);   // uniform addr -> warp broadcast
                v[k] = *(const unsigned long long*)&z[a * D + lane * 2];
            } else {
                v[k] = 0ULL;
            }
        }
        ADD_F32X2(acc0, acc0, v[0]);  ADD_F32X2(acc1, acc1, v[1]);
        ADD_F32X2(acc0, acc0, v[2]);  ADD_F32X2(acc1, acc1, v[3]);
        ADD_F32X2(acc0, acc0, v[4]);  ADD_F32X2(acc1, acc1, v[5]);
        ADD_F32X2(acc0, acc0, v[6]);  ADD_F32X2(acc1, acc1, v[7]);
    }
    ADD_F32X2(acc0, acc0, acc1);
    float2 r;
    asm("mov.b64 {%0, %1}, %2;" : "=f"(r.x), "=f"(r.y) : "l"(acc0));
    return r;
}

// ---------------- agg + bias + relu ----------------
__global__ __launch_bounds__(256)
void agg_relu_kernel(const float* __restrict__ z, float* __restrict__ h,
                     const float* __restrict__ bvec) {
    int node = blockIdx.x * 8 + (threadIdx.x >> 5);
    int lane = threadIdx.x & 31;

    float2 acc = agg_node(z, node, lane);
    float2 b2 = *(const float2*)&bvec[lane * 2];
    acc.x = fmaxf(acc.x + b2.x, 0.f);
    acc.y = fmaxf(acc.y + b2.y, 0.f);
    *(float2*)&h[node * D + lane * 2] = acc;
}

// ---------------- GEMM: z2 = h @ W^T (packed f32x2 FMA) ----------------
#define GEMM_GRID 500
__global__ __launch_bounds__(256, 2)
void gemm_kernel(const float* __restrict__ in, float* __restrict__ out,
                 const float* __restrict__ W) {
    __shared__ __align__(16) float xs[8][D];
    int tid = threadIdx.x;
    int sub = tid >> 6;
    int t   = tid & 63;

    unsigned long long w2[32];
    const unsigned long long* Wp = (const unsigned long long*)(W + t * D);
    #pragma unroll
    for (int k = 0; k < 32; k++) w2[k] = Wp[k];

    for (int base = blockIdx.x * 8; base < N_NODES; base += GEMM_GRID * 8) {
        #pragma unroll
        for (int i = tid; i < 8 * D; i += 256) xs[i >> 6][i & 63] = in[base * D + i];
        __syncthreads();

        #pragma unroll
        for (int r = 0; r < 2; r++) {
            int n = sub * 2 + r;
            const unsigned long long* x = (const unsigned long long*)xs[n];
            unsigned long long a0 = 0ULL, a1 = 0ULL;
            #pragma unroll
            for (int d = 0; d < 32; d += 2) {
                FMA_F32X2(a0, x[d],     w2[d],     a0);
                FMA_F32X2(a1, x[d + 1], w2[d + 1], a1);
            }
            float ax, ay, bx, by;
            asm("mov.b64 {%0, %1}, %2;" : "=f"(ax), "=f"(ay) : "l"(a0));
            asm("mov.b64 {%0, %1}, %2;" : "=f"(bx), "=f"(by) : "l"(a1));
            out[(base + n) * D + t] = (ax + ay) + (bx + by);
        }
        __syncthreads();
    }
}

// ---------------- fused final: agg + bias + relu + cosine ----------------
__global__ __launch_bounds__(256)
void agg_cos_kernel(const float* __restrict__ z,
                    const float* __restrict__ bvec,
                    const float* __restrict__ pattern_emb,
                    const int* __restrict__ pid,
                    float* __restrict__ out) {
    int node = blockIdx.x * 8 + (threadIdx.x >> 5);
    int lane = threadIdx.x & 31;

    float2 acc = agg_node(z, node, lane);
    float2 b2 = *(const float2*)&bvec[lane * 2];
    acc.x = fmaxf(acc.x + b2.x, 0.f);
    acc.y = fmaxf(acc.y + b2.y, 0.f);

    int p_id = __ldg(pid);
    float2 pv = *(const float2*)&pattern_emb[p_id * D + lane * 2];

    float num = acc.x * pv.x + acc.y * pv.y;
    float sq  = acc.x * acc.x + acc.y * acc.y;
    float psq = pv.x * pv.x + pv.y * pv.y;

    #pragma unroll
    for (int o = 16; o > 0; o >>= 1) {
        num += __shfl_xor_sync(0xFFFFFFFFu, num, o);
        sq  += __shfl_xor_sync(0xFFFFFFFFu, sq, o);
        psq += __shfl_xor_sync(0xFFFFFFFFu, psq, o);
    }
    if (lane == 0) {
        float denom = fmaxf(sqrtf(sq), EPS) * fmaxf(sqrtf(psq), EPS);
        out[node] = num / denom;
    }
}

// ---------------- launch ----------------
extern "C" void kernel_launch(void* const* d_in, const int* in_sizes, int n_in,
                              void* d_out, int out_size) {
    const int*   nodes       = (const int*)d_in[0];
    const int2*  edges       = (const int2*)d_in[1];
    const float* features    = (const float*)d_in[2];
    const float* node_emb    = (const float*)d_in[3];
    const float* feat_W      = (const float*)d_in[4];
    const float* feat_b      = (const float*)d_in[5];
    const float* conv1_W     = (const float*)d_in[6];
    const float* conv1_b     = (const float*)d_in[7];
    const float* pattern_emb = (const float*)d_in[8];
    const int*   pattern_id  = (const int*)d_in[9];
    float*       out         = (float*)d_out;

    float* z; float* h; float* z2;
    cudaGetSymbolAddress((void**)&z,  g_z);
    cudaGetSymbolAddress((void**)&h,  g_h);
    cudaGetSymbolAddress((void**)&z2, g_z2);

    // 1: CSR build + folded weights (persistent)
    csr_build_kernel<<<NB, BT>>>(edges, node_emb, feat_W, feat_b, conv1_W);
    // 2: z1
    z1_kernel<<<(N_NODES * 16) / 256, 256>>>(nodes, features);
    // 3: layer-1 agg + relu
    agg_relu_kernel<<<N_NODES / 8, 256>>>(z, h, conv1_b);
    // 4: layer-2 linear (ncu sampling lands here)
    gemm_kernel<<<GEMM_GRID, 256>>>(h, z2, conv1_W);
    // 5: layer-2 agg + relu + cosine
    agg_cos_kernel<<<N_NODES / 8, 256>>>(z2, conv1_b, pattern_emb, pattern_id, out);
}

// round 8
// speedup vs baseline: 2.0931x; 1.0503x over previous
#include <cuda_runtime.h>
#include <cuda_bf16.h>
#include <math.h>

#define N_NODES 100000
#define N_EDGES 800000
#define D 64
#define D_FEAT 10
#define VOCAB 100
#define EPS 1e-8f

#define NB 148     // persistent CSR blocks
#define BT 256
#define CHUNK 676  // ceil(N_NODES / NB)

// packed fp32x2 ops (sm_100+; ptxas only emits via explicit PTX)
#define FMA_F32X2(out, a, b, c) \
    asm("fma.rn.f32x2 %0, %1, %2, %3;" : "=l"(out) : "l"(a), "l"(b), "l"(c))
#define ADD_F32X2(out, a, b) \
    asm("add.rn.f32x2 %0, %1, %2;" : "=l"(out) : "l"(a), "l"(b))

// ---------------- static device scratch ----------------
__device__ float g_z[N_NODES * D];
__device__ float g_h[N_NODES * D];
__device__ float g_z2[N_NODES * D];
__device__ int   g_indeg[N_NODES];
__device__ int   g_off[N_NODES + 1];
__device__ int   g_cursor[N_NODES];
__device__ int   g_srcs[N_EDGES];
__device__ float g_nv[VOCAB * D];
__device__ float g_fw2t[D_FEAT * D];
__device__ float g_c[D];
__device__ unsigned int g_barrier[8];   // zero-init; atomicInc wraps to 0 each replay
__device__ int g_bsum[NB];
__device__ int g_bbase[NB];

// ---------------- grid barrier (self-resetting) ----------------
__device__ __forceinline__ void gbar(int i) {
    __syncthreads();
    if (threadIdx.x == 0) {
        __threadfence();
        atomicInc(&g_barrier[i], NB - 1u);
        volatile unsigned int* p = &g_barrier[i];
        while (*p != 0u) __nanosleep(32);
        __threadfence();
    }
    __syncthreads();
}

// ---------------- CSR build + folded-weight precompute (one persistent kernel) ----------------
#define WP 65
__global__ __launch_bounds__(BT)
void csr_build_kernel(const int2* __restrict__ edges,
                      const float* __restrict__ node_emb,
                      const float* __restrict__ feat_W,
                      const float* __restrict__ feat_b,
                      const float* __restrict__ W) {
    int tid  = threadIdx.x;
    int b    = blockIdx.x;
    int lane = tid & 31;
    int w    = tid >> 5;
    int gt   = b * BT + tid;
    const int gs = NB * BT;

    __shared__ int sm8[8];

    // phase 0: blocks 0..25 compute folded weights (read only by later z1 kernel)
    if (b <= 25) {
        __shared__ float sW[D * WP];
        for (int i = tid; i < D * D; i += BT) sW[(i >> 6) * WP + (i & 63)] = W[i];
        if (b == 0) {
            __shared__ float sFW[D * D_FEAT];
            __shared__ float sFB[D];
            for (int i = tid; i < D * D_FEAT; i += BT) sFW[i] = feat_W[i];
            if (tid < D) sFB[tid] = feat_b[tid];
            __syncthreads();
            for (int i = tid; i < D_FEAT * D; i += BT) {
                int k = i / D, d = i % D;
                float s = 0.f;
                #pragma unroll
                for (int j = 0; j < D; j++) s += sW[d * WP + j] * sFW[j * D_FEAT + k];
                g_fw2t[k * D + d] = s;
            }
            if (tid < D) {
                float cb = 0.f;
                #pragma unroll
                for (int j = 0; j < D; j++) cb += sW[tid * WP + j] * sFB[j];
                g_c[tid] = cb;
            }
        } else {
            __shared__ float sE[4][D];
            int v0 = (b - 1) * 4;
            if (tid < 4 * D) sE[tid >> 6][tid & 63] = node_emb[v0 * D + tid];
            __syncthreads();
            int vl = tid >> 6;
            int d  = tid & 63;
            float s = 0.f;
            #pragma unroll
            for (int j = 0; j < D; j++) s += sW[d * WP + j] * sE[vl][j];
            g_nv[(v0 + vl) * D + d] = s;
        }
        __syncthreads();
    }

    // phase 1: zero indeg
    for (int i = gt; i < N_NODES; i += gs) g_indeg[i] = 0;
    gbar(0);

    // phase 2: count
    for (int e = gt; e < N_EDGES; e += gs) atomicAdd(&g_indeg[edges[e].y], 1);
    gbar(1);

    // phase 3: per-block partial sums
    int cs = b * CHUNK;
    int ce = min(cs + CHUNK, N_NODES);
    {
        int s = 0;
        for (int i = cs + tid; i < ce; i += BT) s += g_indeg[i];
        #pragma unroll
        for (int o = 16; o; o >>= 1) s += __shfl_xor_sync(0xFFFFFFFFu, s, o);
        if (lane == 0) sm8[w] = s;
        __syncthreads();
        if (tid == 0) {
            int t = 0;
            #pragma unroll
            for (int k = 0; k < 8; k++) t += sm8[k];
            g_bsum[b] = t;
        }
    }
    gbar(2);

    // phase 4: block 0 scans block sums
    if (b == 0) {
        int x = (tid < NB) ? g_bsum[tid] : 0;
        int incl = x;
        #pragma unroll
        for (int o = 1; o < 32; o <<= 1) {
            int n = __shfl_up_sync(0xFFFFFFFFu, incl, o);
            if (lane >= o) incl += n;
        }
        __syncthreads();
        if (lane == 31) sm8[w] = incl;
        __syncthreads();
        if (w == 0 && lane < 8) {
            int v = sm8[lane];
            #pragma unroll
            for (int o = 1; o < 8; o <<= 1) {
                int n = __shfl_up_sync(0xFFu, v, o);
                if (lane >= o) v += n;
            }
            sm8[lane] = v;
        }
        __syncthreads();
        int excl = incl - x + (w ? sm8[w - 1] : 0);
        if (tid < NB) g_bbase[tid] = excl;
    }
    gbar(3);

    // phase 5: per-block tile scans -> off, cursor
    {
        int run = g_bbase[b];
        for (int t0 = cs; t0 < cs + CHUNK; t0 += BT) {
            int i = t0 + tid;
            int x = (i < ce) ? g_indeg[i] : 0;
            int incl = x;
            #pragma unroll
            for (int o = 1; o < 32; o <<= 1) {
                int n = __shfl_up_sync(0xFFFFFFFFu, incl, o);
                if (lane >= o) incl += n;
            }
            __syncthreads();
            if (lane == 31) sm8[w] = incl;
            __syncthreads();
            if (w == 0 && lane < 8) {
                int v = sm8[lane];
                #pragma unroll
                for (int o = 1; o < 8; o <<= 1) {
                    int n = __shfl_up_sync(0xFFu, v, o);
                    if (lane >= o) v += n;
                }
                sm8[lane] = v;
            }
            __syncthreads();
            int excl = incl - x + (w ? sm8[w - 1] : 0) + run;
            if (i < ce) { g_off[i] = excl; g_cursor[i] = excl; }
            run += sm8[7];
        }
        if (b == 0 && tid == 0) g_off[N_NODES] = N_EDGES;
    }
    gbar(4);

    // phase 6: place
    for (int e = gt; e < N_EDGES; e += gs) {
        int2 ed = edges[e];
        int slot = atomicAdd(&g_cursor[ed.y], 1);
        g_srcs[slot] = ed.x;
    }
}

// ---------------- z1 = nv[nodes] + features @ fw2^T + c ----------------
__global__ __launch_bounds__(256)
void z1_kernel(const int* __restrict__ nodes, const float* __restrict__ features) {
    __shared__ float s_fw2t[D_FEAT * D];
    __shared__ float s_c[D];
    int tid = threadIdx.x;
    for (int i = tid; i < D_FEAT * D; i += 256) s_fw2t[i] = g_fw2t[i];
    if (tid < D) s_c[tid] = g_c[tid];
    __syncthreads();

    int q    = blockIdx.x * 256 + tid;
    int node = q >> 4;
    int dq   = (q & 15) * 4;

    int tok = __ldg(&nodes[node]);
    const float* f = features + node * D_FEAT;
    float fk[D_FEAT];
    #pragma unroll
    for (int k = 0; k < D_FEAT; k++) fk[k] = f[k];

    float4 acc = *(const float4*)&g_nv[tok * D + dq];
    float4 cc  = *(const float4*)&s_c[dq];
    acc.x += cc.x; acc.y += cc.y; acc.z += cc.z; acc.w += cc.w;

    #pragma unroll
    for (int k = 0; k < D_FEAT; k++) {
        float4 w4 = *(const float4*)&s_fw2t[k * D + dq];
        acc.x += fk[k] * w4.x; acc.y += fk[k] * w4.y;
        acc.z += fk[k] * w4.z; acc.w += fk[k] * w4.w;
    }
    *(float4*)&g_z[node * D + dq] = acc;
}

// ---------------- aggregation: shfl-free, 8 independent idx->row chains ----------------
__device__ __forceinline__ float2 agg_node(const float* __restrict__ z,
                                           int node, int lane) {
    unsigned long long acc0 =
        *(const unsigned long long*)&z[node * D + lane * 2];
    unsigned long long acc1 = 0ULL;
    int s0 = __ldg(&g_off[node]);
    int s1 = __ldg(&g_off[node + 1]);

    for (int j = s0; j < s1; j += 8) {
        unsigned long long v[8];
        #pragma unroll
        for (int k = 0; k < 8; k++) {
            if (j + k < s1) {
                int a = __ldg(&g_srcs[j + k]);   // uniform addr -> warp broadcast
                v[k] = *(const unsigned long long*)&z[a * D + lane * 2];
            } else {
                v[k] = 0ULL;
            }
        }
        ADD_F32X2(acc0, acc0, v[0]);  ADD_F32X2(acc1, acc1, v[1]);
        ADD_F32X2(acc0, acc0, v[2]);  ADD_F32X2(acc1, acc1, v[3]);
        ADD_F32X2(acc0, acc0, v[4]);  ADD_F32X2(acc1, acc1, v[5]);
        ADD_F32X2(acc0, acc0, v[6]);  ADD_F32X2(acc1, acc1, v[7]);
    }
    ADD_F32X2(acc0, acc0, acc1);
    float2 r;
    asm("mov.b64 {%0, %1}, %2;" : "=f"(r.x), "=f"(r.y) : "l"(acc0));
    return r;
}

// ---------------- agg + bias + relu ----------------
__global__ __launch_bounds__(256)
void agg_relu_kernel(const float* __restrict__ z, float* __restrict__ h,
                     const float* __restrict__ bvec) {
    int node = blockIdx.x * 8 + (threadIdx.x >> 5);
    int lane = threadIdx.x & 31;

    float2 acc = agg_node(z, node, lane);
    float2 b2 = *(const float2*)&bvec[lane * 2];
    acc.x = fmaxf(acc.x + b2.x, 0.f);
    acc.y = fmaxf(acc.y + b2.y, 0.f);
    *(float2*)&h[node * D + lane * 2] = acc;
}

// ---------------- GEMM: z2 = h @ W^T ----------------
// 128 threads = 2 teams x 64. Thread owns output dim t (W row in regs, packed).
// 8 nodes/tile/team, 8 independent f32x2 accumulator chains per thread.
#define GEMM_GRID 592
#define N_TILES (N_NODES / 16)   // 6250 tiles of 16 nodes (2 teams x 8)
__global__ __launch_bounds__(128, 4)
void gemm_kernel(const float* __restrict__ in, float* __restrict__ out,
                 const float* __restrict__ W) {
    __shared__ __align__(16) float xs[2][8][D];
    int tid  = threadIdx.x;
    int team = tid >> 6;
    int t    = tid & 63;

    unsigned long long w2[32];
    const unsigned long long* Wp = (const unsigned long long*)(W + t * D);
    #pragma unroll
    for (int k = 0; k < 32; k++) w2[k] = Wp[k];

    for (int tile = blockIdx.x; tile < N_TILES; tile += GEMM_GRID) {
        int base = tile * 16;            // block covers nodes [base, base+16)
        // cooperative tile load: 16 rows x 64 floats = 256 float4, 2 per thread
        const float4* src = (const float4*)(in + base * D);
        float4* dst = (float4*)&xs[0][0][0];
        dst[tid]       = src[tid];
        dst[tid + 128] = src[tid + 128];
        __syncthreads();

        const unsigned long long* x = (const unsigned long long*)&xs[team][0][0];
        unsigned long long acc[8];
        #pragma unroll
        for (int n = 0; n < 8; n++) acc[n] = 0ULL;

        #pragma unroll 8
        for (int dp = 0; dp < 32; dp++) {
            unsigned long long wv = w2[dp];
            #pragma unroll
            for (int n = 0; n < 8; n++) {
                FMA_F32X2(acc[n], x[n * 32 + dp], wv, acc[n]);
            }
        }

        int nb = base + team * 8;
        #pragma unroll
        for (int n = 0; n < 8; n++) {
            float lo, hi;
            asm("mov.b64 {%0, %1}, %2;" : "=f"(lo), "=f"(hi) : "l"(acc[n]));
            out[(nb + n) * D + t] = lo + hi;
        }
        __syncthreads();
    }
}

// ---------------- fused final: agg + bias + relu + cosine ----------------
__global__ __launch_bounds__(256)
void agg_cos_kernel(const float* __restrict__ z,
                    const float* __restrict__ bvec,
                    const float* __restrict__ pattern_emb,
                    const int* __restrict__ pid,
                    float* __restrict__ out) {
    int node = blockIdx.x * 8 + (threadIdx.x >> 5);
    int lane = threadIdx.x & 31;

    float2 acc = agg_node(z, node, lane);
    float2 b2 = *(const float2*)&bvec[lane * 2];
    acc.x = fmaxf(acc.x + b2.x, 0.f);
    acc.y = fmaxf(acc.y + b2.y, 0.f);

    int p_id = __ldg(pid);
    float2 pv = *(const float2*)&pattern_emb[p_id * D + lane * 2];

    float num = acc.x * pv.x + acc.y * pv.y;
    float sq  = acc.x * acc.x + acc.y * acc.y;
    float psq = pv.x * pv.x + pv.y * pv.y;

    #pragma unroll
    for (int o = 16; o > 0; o >>= 1) {
        num += __shfl_xor_sync(0xFFFFFFFFu, num, o);
        sq  += __shfl_xor_sync(0xFFFFFFFFu, sq, o);
        psq += __shfl_xor_sync(0xFFFFFFFFu, psq, o);
    }
    if (lane == 0) {
        float denom = fmaxf(sqrtf(sq), EPS) * fmaxf(sqrtf(psq), EPS);
        out[node] = num / denom;
    }
}

// ---------------- launch ----------------
extern "C" void kernel_launch(void* const* d_in, const int* in_sizes, int n_in,
                              void* d_out, int out_size) {
    const int*   nodes       = (const int*)d_in[0];
    const int2*  edges       = (const int2*)d_in[1];
    const float* features    = (const float*)d_in[2];
    const float* node_emb    = (const float*)d_in[3];
    const float* feat_W      = (const float*)d_in[4];
    const float* feat_b      = (const float*)d_in[5];
    const float* conv1_W     = (const float*)d_in[6];
    const float* conv1_b     = (const float*)d_in[7];
    const float* pattern_emb = (const float*)d_in[8];
    const int*   pattern_id  = (const int*)d_in[9];
    float*       out         = (float*)d_out;

    float* z; float* h; float* z2;
    cudaGetSymbolAddress((void**)&z,  g_z);
    cudaGetSymbolAddress((void**)&h,  g_h);
    cudaGetSymbolAddress((void**)&z2, g_z2);

    // 1: CSR build + folded weights (persistent)
    csr_build_kernel<<<NB, BT>>>(edges, node_emb, feat_W, feat_b, conv1_W);
    // 2: z1
    z1_kernel<<<(N_NODES * 16) / 256, 256>>>(nodes, features);
    // 3: layer-1 agg + relu
    agg_relu_kernel<<<N_NODES / 8, 256>>>(z, h, conv1_b);
    // 4: layer-2 linear (ncu sampling lands here)
    gemm_kernel<<<GEMM_GRID, 128>>>(h, z2, conv1_W);
    // 5: layer-2 agg + relu + cosine
    agg_cos_kernel<<<N_NODES / 8, 256>>>(z2, conv1_b, pattern_emb, pattern_id, out);
}

// round 9
// speedup vs baseline: 2.1329x; 1.0191x over previous
#include <cuda_runtime.h>
#include <cuda_bf16.h>
#include <math.h>

#define N_NODES 100000
#define N_EDGES 800000
#define D 64
#define D_FEAT 10
#define VOCAB 100
#define EPS 1e-8f

#define NB 148     // persistent CSR blocks
#define BT 256
#define CHUNK 676  // ceil(N_NODES / NB)

// packed fp32x2 ops (sm_100+; ptxas only emits via explicit PTX)
#define FMA_F32X2(out, a, b, c) \
    asm("fma.rn.f32x2 %0, %1, %2, %3;" : "=l"(out) : "l"(a), "l"(b), "l"(c))
#define ADD_F32X2(out, a, b) \
    asm("add.rn.f32x2 %0, %1, %2;" : "=l"(out) : "l"(a), "l"(b))

// ---------------- static device scratch ----------------
__device__ float g_z[N_NODES * D];
__device__ float g_h[N_NODES * D];
__device__ float g_z2[N_NODES * D];
__device__ int   g_indeg[N_NODES];
__device__ int   g_off[N_NODES + 1];
__device__ int   g_cursor[N_NODES];
__device__ int   g_srcs[N_EDGES];
__device__ float g_nv[VOCAB * D];
__device__ float g_fw2t[D_FEAT * D];
__device__ float g_c[D];
__device__ unsigned int g_barrier[8];   // zero-init; atomicInc wraps to 0 each replay
__device__ int g_bsum[NB];
__device__ int g_bbase[NB];

// ---------------- grid barrier (self-resetting) ----------------
__device__ __forceinline__ void gbar(int i) {
    __syncthreads();
    if (threadIdx.x == 0) {
        __threadfence();
        atomicInc(&g_barrier[i], NB - 1u);
        volatile unsigned int* p = &g_barrier[i];
        while (*p != 0u) __nanosleep(32);
        __threadfence();
    }
    __syncthreads();
}

// ---------------- CSR build + folded-weight precompute (one persistent kernel) ----------------
#define WP 65
__global__ __launch_bounds__(BT)
void csr_build_kernel(const int2* __restrict__ edges,
                      const float* __restrict__ node_emb,
                      const float* __restrict__ feat_W,
                      const float* __restrict__ feat_b,
                      const float* __restrict__ W) {
    int tid  = threadIdx.x;
    int b    = blockIdx.x;
    int lane = tid & 31;
    int w    = tid >> 5;
    int gt   = b * BT + tid;
    const int gs = NB * BT;

    __shared__ int sm8[8];

    // phase 0: blocks 0..25 compute folded weights
    if (b <= 25) {
        __shared__ float sW[D * WP];
        for (int i = tid; i < D * D; i += BT) sW[(i >> 6) * WP + (i & 63)] = W[i];
        if (b == 0) {
            __shared__ float sFW[D * D_FEAT];
            __shared__ float sFB[D];
            for (int i = tid; i < D * D_FEAT; i += BT) sFW[i] = feat_W[i];
            if (tid < D) sFB[tid] = feat_b[tid];
            __syncthreads();
            for (int i = tid; i < D_FEAT * D; i += BT) {
                int k = i / D, d = i % D;
                float s = 0.f;
                #pragma unroll
                for (int j = 0; j < D; j++) s += sW[d * WP + j] * sFW[j * D_FEAT + k];
                g_fw2t[k * D + d] = s;
            }
            if (tid < D) {
                float cb = 0.f;
                #pragma unroll
                for (int j = 0; j < D; j++) cb += sW[tid * WP + j] * sFB[j];
                g_c[tid] = cb;
            }
        } else {
            __shared__ float sE[4][D];
            int v0 = (b - 1) * 4;
            if (tid < 4 * D) sE[tid >> 6][tid & 63] = node_emb[v0 * D + tid];
            __syncthreads();
            int vl = tid >> 6;
            int d  = tid & 63;
            float s = 0.f;
            #pragma unroll
            for (int j = 0; j < D; j++) s += sW[d * WP + j] * sE[vl][j];
            g_nv[(v0 + vl) * D + d] = s;
        }
        __syncthreads();
    }

    // phase 1: zero indeg
    for (int i = gt; i < N_NODES; i += gs) g_indeg[i] = 0;
    gbar(0);

    // phase 2: count
    for (int e = gt; e < N_EDGES; e += gs) atomicAdd(&g_indeg[edges[e].y], 1);
    gbar(1);

    // phase 3: per-block partial sums
    int cs = b * CHUNK;
    int ce = min(cs + CHUNK, N_NODES);
    {
        int s = 0;
        for (int i = cs + tid; i < ce; i += BT) s += g_indeg[i];
        #pragma unroll
        for (int o = 16; o; o >>= 1) s += __shfl_xor_sync(0xFFFFFFFFu, s, o);
        if (lane == 0) sm8[w] = s;
        __syncthreads();
        if (tid == 0) {
            int t = 0;
            #pragma unroll
            for (int k = 0; k < 8; k++) t += sm8[k];
            g_bsum[b] = t;
        }
    }
    gbar(2);

    // phase 4: block 0 scans block sums
    if (b == 0) {
        int x = (tid < NB) ? g_bsum[tid] : 0;
        int incl = x;
        #pragma unroll
        for (int o = 1; o < 32; o <<= 1) {
            int n = __shfl_up_sync(0xFFFFFFFFu, incl, o);
            if (lane >= o) incl += n;
        }
        __syncthreads();
        if (lane == 31) sm8[w] = incl;
        __syncthreads();
        if (w == 0 && lane < 8) {
            int v = sm8[lane];
            #pragma unroll
            for (int o = 1; o < 8; o <<= 1) {
                int n = __shfl_up_sync(0xFFu, v, o);
                if (lane >= o) v += n;
            }
            sm8[lane] = v;
        }
        __syncthreads();
        int excl = incl - x + (w ? sm8[w - 1] : 0);
        if (tid < NB) g_bbase[tid] = excl;
    }
    gbar(3);

    // phase 5: per-block tile scans -> off, cursor
    {
        int run = g_bbase[b];
        for (int t0 = cs; t0 < cs + CHUNK; t0 += BT) {
            int i = t0 + tid;
            int x = (i < ce) ? g_indeg[i] : 0;
            int incl = x;
            #pragma unroll
            for (int o = 1; o < 32; o <<= 1) {
                int n = __shfl_up_sync(0xFFFFFFFFu, incl, o);
                if (lane >= o) incl += n;
            }
            __syncthreads();
            if (lane == 31) sm8[w] = incl;
            __syncthreads();
            if (w == 0 && lane < 8) {
                int v = sm8[lane];
                #pragma unroll
                for (int o = 1; o < 8; o <<= 1) {
                    int n = __shfl_up_sync(0xFFu, v, o);
                    if (lane >= o) v += n;
                }
                sm8[lane] = v;
            }
            __syncthreads();
            int excl = incl - x + (w ? sm8[w - 1] : 0) + run;
            if (i < ce) { g_off[i] = excl; g_cursor[i] = excl; }
            run += sm8[7];
        }
        if (b == 0 && tid == 0) g_off[N_NODES] = N_EDGES;
    }
    gbar(4);

    // phase 6: place
    for (int e = gt; e < N_EDGES; e += gs) {
        int2 ed = edges[e];
        int slot = atomicAdd(&g_cursor[ed.y], 1);
        g_srcs[slot] = ed.x;
    }
}

// ---------------- z1 = nv[nodes] + features @ fw2^T + c ----------------
__global__ __launch_bounds__(256)
void z1_kernel(const int* __restrict__ nodes, const float* __restrict__ features) {
    __shared__ float s_fw2t[D_FEAT * D];
    __shared__ float s_c[D];
    int tid = threadIdx.x;
    for (int i = tid; i < D_FEAT * D; i += 256) s_fw2t[i] = g_fw2t[i];
    if (tid < D) s_c[tid] = g_c[tid];
    __syncthreads();

    int q    = blockIdx.x * 256 + tid;
    int node = q >> 4;
    int dq   = (q & 15) * 4;

    int tok = __ldg(&nodes[node]);
    const float* f = features + node * D_FEAT;
    float fk[D_FEAT];
    #pragma unroll
    for (int k = 0; k < D_FEAT; k++) fk[k] = f[k];

    float4 acc = *(const float4*)&g_nv[tok * D + dq];
    float4 cc  = *(const float4*)&s_c[dq];
    acc.x += cc.x; acc.y += cc.y; acc.z += cc.z; acc.w += cc.w;

    #pragma unroll
    for (int k = 0; k < D_FEAT; k++) {
        float4 w4 = *(const float4*)&s_fw2t[k * D + dq];
        acc.x += fk[k] * w4.x; acc.y += fk[k] * w4.y;
        acc.z += fk[k] * w4.z; acc.w += fk[k] * w4.w;
    }
    *(float4*)&g_z[node * D + dq] = acc;
}

// ---------------- aggregation: shfl-free, 8 independent idx->row chains ----------------
__device__ __forceinline__ float2 agg_node(const float* __restrict__ z,
                                           int node, int lane) {
    unsigned long long acc0 =
        *(const unsigned long long*)&z[node * D + lane * 2];
    unsigned long long acc1 = 0ULL;
    int s0 = __ldg(&g_off[node]);
    int s1 = __ldg(&g_off[node + 1]);

    for (int j = s0; j < s1; j += 8) {
        unsigned long long v[8];
        #pragma unroll
        for (int k = 0; k < 8; k++) {
            if (j + k < s1) {
                int a = __ldg(&g_srcs[j + k]);   // uniform addr -> warp broadcast
                v[k] = *(const unsigned long long*)&z[a * D + lane * 2];
            } else {
                v[k] = 0ULL;
            }
        }
        ADD_F32X2(acc0, acc0, v[0]);  ADD_F32X2(acc1, acc1, v[1]);
        ADD_F32X2(acc0, acc0, v[2]);  ADD_F32X2(acc1, acc1, v[3]);
        ADD_F32X2(acc0, acc0, v[4]);  ADD_F32X2(acc1, acc1, v[5]);
        ADD_F32X2(acc0, acc0, v[6]);  ADD_F32X2(acc1, acc1, v[7]);
    }
    ADD_F32X2(acc0, acc0, acc1);
    float2 r;
    asm("mov.b64 {%0, %1}, %2;" : "=f"(r.x), "=f"(r.y) : "l"(acc0));
    return r;
}

// ---------------- agg + bias + relu ----------------
__global__ __launch_bounds__(256)
void agg_relu_kernel(const float* __restrict__ z, float* __restrict__ h,
                     const float* __restrict__ bvec) {
    int node = blockIdx.x * 8 + (threadIdx.x >> 5);
    int lane = threadIdx.x & 31;

    float2 acc = agg_node(z, node, lane);
    float2 b2 = *(const float2*)&bvec[lane * 2];
    acc.x = fmaxf(acc.x + b2.x, 0.f);
    acc.y = fmaxf(acc.y + b2.y, 0.f);
    *(float2*)&h[node * D + lane * 2] = acc;
}

// ---------------- GEMM: z2 = h @ W^T ----------------
// 128 threads = 2 teams x 64. Thread owns output dim t (W row in regs, packed).
// 8 nodes/tile/team, 8 independent f32x2 chains; x via LDS.128 (ulonglong2);
// register double-buffer hides the global tile load.
#define GEMM_GRID 592
#define N_TILES (N_NODES / 16)   // 6250 tiles of 16 nodes
__global__ __launch_bounds__(128, 4)
void gemm_kernel(const float* __restrict__ in, float* __restrict__ out,
                 const float* __restrict__ W) {
    __shared__ __align__(16) float xs[16][D];
    int tid  = threadIdx.x;
    int team = tid >> 6;
    int t    = tid & 63;

    unsigned long long w2[32];
    const unsigned long long* Wp = (const unsigned long long*)(W + t * D);
    #pragma unroll
    for (int k = 0; k < 32; k++) w2[k] = Wp[k];

    const float4* src = (const float4*)in;
    int tile = blockIdx.x;
    float4 r0, r1;
    if (tile < N_TILES) {
        r0 = src[tile * 256 + tid];
        r1 = src[tile * 256 + tid + 128];
    }

    for (; tile < N_TILES; tile += GEMM_GRID) {
        ((float4*)xs)[tid]       = r0;
        ((float4*)xs)[tid + 128] = r1;
        __syncthreads();

        // prefetch next tile while computing this one
        int nt = tile + GEMM_GRID;
        if (nt < N_TILES) {
            r0 = src[nt * 256 + tid];
            r1 = src[nt * 256 + tid + 128];
        }

        const ulonglong2* x = (const ulonglong2*)&xs[team * 8][0];  // 16 ull2 per node
        unsigned long long acc[8];
        #pragma unroll
        for (int n = 0; n < 8; n++) acc[n] = 0ULL;

        #pragma unroll 4
        for (int dp = 0; dp < 16; dp++) {
            unsigned long long w0 = w2[2 * dp], w1 = w2[2 * dp + 1];
            #pragma unroll
            for (int n = 0; n < 8; n++) {
                ulonglong2 xv = x[n * 16 + dp];          // LDS.128 broadcast
                FMA_F32X2(acc[n], xv.x, w0, acc[n]);
                FMA_F32X2(acc[n], xv.y, w1, acc[n]);
            }
        }

        int nb = tile * 16 + team * 8;
        #pragma unroll
        for (int n = 0; n < 8; n++) {
            float lo, hi;
            asm("mov.b64 {%0, %1}, %2;" : "=f"(lo), "=f"(hi) : "l"(acc[n]));
            out[(nb + n) * D + t] = lo + hi;
        }
        __syncthreads();
    }
}

// ---------------- fused final: agg + bias + relu + cosine ----------------
__global__ __launch_bounds__(256)
void agg_cos_kernel(const float* __restrict__ z,
                    const float* __restrict__ bvec,
                    const float* __restrict__ pattern_emb,
                    const int* __restrict__ pid,
                    float* __restrict__ out) {
    int node = blockIdx.x * 8 + (threadIdx.x >> 5);
    int lane = threadIdx.x & 31;

    float2 acc = agg_node(z, node, lane);
    float2 b2 = *(const float2*)&bvec[lane * 2];
    acc.x = fmaxf(acc.x + b2.x, 0.f);
    acc.y = fmaxf(acc.y + b2.y, 0.f);

    int p_id = __ldg(pid);
    float2 pv = *(const float2*)&pattern_emb[p_id * D + lane * 2];

    float num = acc.x * pv.x + acc.y * pv.y;
    float sq  = acc.x * acc.x + acc.y * acc.y;
    float psq = pv.x * pv.x + pv.y * pv.y;

    #pragma unroll
    for (int o = 16; o > 0; o >>= 1) {
        num += __shfl_xor_sync(0xFFFFFFFFu, num, o);
        sq  += __shfl_xor_sync(0xFFFFFFFFu, sq, o);
        psq += __shfl_xor_sync(0xFFFFFFFFu, psq, o);
    }
    if (lane == 0) {
        float denom = fmaxf(sqrtf(sq), EPS) * fmaxf(sqrtf(psq), EPS);
        out[node] = num / denom;
    }
}

// ---------------- launch ----------------
extern "C" void kernel_launch(void* const* d_in, const int* in_sizes, int n_in,
                              void* d_out, int out_size) {
    const int*   nodes       = (const int*)d_in[0];
    const int2*  edges       = (const int2*)d_in[1];
    const float* features    = (const float*)d_in[2];
    const float* node_emb    = (const float*)d_in[3];
    const float* feat_W      = (const float*)d_in[4];
    const float* feat_b      = (const float*)d_in[5];
    const float* conv1_W     = (const float*)d_in[6];
    const float* conv1_b     = (const float*)d_in[7];
    const float* pattern_emb = (const float*)d_in[8];
    const int*   pattern_id  = (const int*)d_in[9];
    float*       out         = (float*)d_out;

    float* z; float* h; float* z2;
    cudaGetSymbolAddress((void**)&z,  g_z);
    cudaGetSymbolAddress((void**)&h,  g_h);
    cudaGetSymbolAddress((void**)&z2, g_z2);

    // 1: CSR build + folded weights (persistent)
    csr_build_kernel<<<NB, BT>>>(edges, node_emb, feat_W, feat_b, conv1_W);
    // 2: z1
    z1_kernel<<<(N_NODES * 16) / 256, 256>>>(nodes, features);
    // 3: layer-1 agg + relu
    agg_relu_kernel<<<N_NODES / 8, 256>>>(z, h, conv1_b);
    // 4: layer-2 linear (ncu sampling lands here)
    gemm_kernel<<<GEMM_GRID, 128>>>(h, z2, conv1_W);
    // 5: layer-2 agg + relu + cosine
    agg_cos_kernel<<<N_NODES / 8, 256>>>(z2, conv1_b, pattern_emb, pattern_id, out);
}

// round 10
// speedup vs baseline: 2.2740x; 1.0661x over previous
#include <cuda_runtime.h>
#include <cuda_bf16.h>
#include <math.h>

#define N_NODES 100000
#define N_EDGES 800000
#define D 64
#define D_FEAT 10
#define VOCAB 100
#define EPS 1e-8f

#define NB 148     // persistent CSR blocks
#define BT 256
#define CHUNK 676  // ceil(N_NODES / NB)

// packed fp32x2 ops (sm_100+; ptxas only emits via explicit PTX)
#define FMA_F32X2(out, a, b, c) \
    asm("fma.rn.f32x2 %0, %1, %2, %3;" : "=l"(out) : "l"(a), "l"(b), "l"(c))
#define ADD_F32X2(out, a, b) \
    asm("add.rn.f32x2 %0, %1, %2;" : "=l"(out) : "l"(a), "l"(b))

// ---------------- static device scratch ----------------
__device__ float g_z[N_NODES * D];
__device__ float g_h[N_NODES * D];
__device__ float g_z2[N_NODES * D];
__device__ int   g_indeg[N_NODES];
__device__ int   g_off[N_NODES + 1];
__device__ int   g_cursor[N_NODES];
__device__ int   g_srcs[N_EDGES];
__device__ float g_nv[VOCAB * D];
__device__ float g_fw2t[D_FEAT * D];
__device__ float g_c[D];
__device__ unsigned int g_barrier[8];   // zero-init; atomicInc wraps to 0 each replay
__device__ int g_bsum[NB];
__device__ int g_bbase[NB];

// ---------------- grid barrier (self-resetting) ----------------
__device__ __forceinline__ void gbar(int i) {
    __syncthreads();
    if (threadIdx.x == 0) {
        __threadfence();
        atomicInc(&g_barrier[i], NB - 1u);
        volatile unsigned int* p = &g_barrier[i];
        while (*p != 0u) __nanosleep(32);
        __threadfence();
    }
    __syncthreads();
}

// ---------------- CSR build + folded weights + z1 (one persistent kernel) ----------------
#define WP 65
__global__ __launch_bounds__(BT)
void csr_build_kernel(const int2* __restrict__ edges,
                      const float* __restrict__ node_emb,
                      const float* __restrict__ feat_W,
                      const float* __restrict__ feat_b,
                      const float* __restrict__ W,
                      const int* __restrict__ nodes,
                      const float* __restrict__ features) {
    int tid  = threadIdx.x;
    int b    = blockIdx.x;
    int lane = tid & 31;
    int w    = tid >> 5;
    int gt   = b * BT + tid;
    const int gs = NB * BT;

    __shared__ int sm8[8];
    __shared__ float s_fw2t[D_FEAT * D];
    __shared__ float s_c[D];

    // phase 0: blocks 0..25 compute folded weights
    if (b <= 25) {
        __shared__ float sW[D * WP];
        for (int i = tid; i < D * D; i += BT) sW[(i >> 6) * WP + (i & 63)] = W[i];
        if (b == 0) {
            __shared__ float sFW[D * D_FEAT];
            __shared__ float sFB[D];
            for (int i = tid; i < D * D_FEAT; i += BT) sFW[i] = feat_W[i];
            if (tid < D) sFB[tid] = feat_b[tid];
            __syncthreads();
            for (int i = tid; i < D_FEAT * D; i += BT) {
                int k = i / D, d = i % D;
                float s = 0.f;
                #pragma unroll
                for (int j = 0; j < D; j++) s += sW[d * WP + j] * sFW[j * D_FEAT + k];
                g_fw2t[k * D + d] = s;
            }
            if (tid < D) {
                float cb = 0.f;
                #pragma unroll
                for (int j = 0; j < D; j++) cb += sW[tid * WP + j] * sFB[j];
                g_c[tid] = cb;
            }
        } else {
            __shared__ float sE[4][D];
            int v0 = (b - 1) * 4;
            if (tid < 4 * D) sE[tid >> 6][tid & 63] = node_emb[v0 * D + tid];
            __syncthreads();
            int vl = tid >> 6;
            int d  = tid & 63;
            float s = 0.f;
            #pragma unroll
            for (int j = 0; j < D; j++) s += sW[d * WP + j] * sE[vl][j];
            g_nv[(v0 + vl) * D + d] = s;
        }
        __syncthreads();
    }

    // phase 1: zero indeg
    for (int i = gt; i < N_NODES; i += gs) g_indeg[i] = 0;
    gbar(0);   // precompute + zero globally done

    // phase 2a: z1 = nv[nodes] + features @ fw2^T + c   (grid-stride)
    for (int i = tid; i < D_FEAT * D; i += BT) s_fw2t[i] = g_fw2t[i];
    if (tid < D) s_c[tid] = g_c[tid];
    __syncthreads();
    for (int q = gt; q < N_NODES * 16; q += gs) {
        int node = q >> 4;
        int dq   = (q & 15) * 4;
        int tok  = __ldg(&nodes[node]);
        const float* f = features + node * D_FEAT;
        float fk[D_FEAT];
        #pragma unroll
        for (int k = 0; k < D_FEAT; k++) fk[k] = f[k];

        float4 acc = *(const float4*)&g_nv[tok * D + dq];
        float4 cc  = *(const float4*)&s_c[dq];
        acc.x += cc.x; acc.y += cc.y; acc.z += cc.z; acc.w += cc.w;
        #pragma unroll
        for (int k = 0; k < D_FEAT; k++) {
            float4 w4 = *(const float4*)&s_fw2t[k * D + dq];
            acc.x += fk[k] * w4.x; acc.y += fk[k] * w4.y;
            acc.z += fk[k] * w4.z; acc.w += fk[k] * w4.w;
        }
        *(float4*)&g_z[node * D + dq] = acc;
    }

    // phase 2b: count
    for (int e = gt; e < N_EDGES; e += gs) atomicAdd(&g_indeg[edges[e].y], 1);
    gbar(1);

    // phase 3: per-block partial sums
    int cs = b * CHUNK;
    int ce = min(cs + CHUNK, N_NODES);
    {
        int s = 0;
        for (int i = cs + tid; i < ce; i += BT) s += g_indeg[i];
        #pragma unroll
        for (int o = 16; o; o >>= 1) s += __shfl_xor_sync(0xFFFFFFFFu, s, o);
        if (lane == 0) sm8[w] = s;
        __syncthreads();
        if (tid == 0) {
            int t = 0;
            #pragma unroll
            for (int k = 0; k < 8; k++) t += sm8[k];
            g_bsum[b] = t;
        }
    }
    gbar(2);

    // phase 4: block 0 scans block sums
    if (b == 0) {
        int x = (tid < NB) ? g_bsum[tid] : 0;
        int incl = x;
        #pragma unroll
        for (int o = 1; o < 32; o <<= 1) {
            int n = __shfl_up_sync(0xFFFFFFFFu, incl, o);
            if (lane >= o) incl += n;
        }
        __syncthreads();
        if (lane == 31) sm8[w] = incl;
        __syncthreads();
        if (w == 0 && lane < 8) {
            int v = sm8[lane];
            #pragma unroll
            for (int o = 1; o < 8; o <<= 1) {
                int n = __shfl_up_sync(0xFFu, v, o);
                if (lane >= o) v += n;
            }
            sm8[lane] = v;
        }
        __syncthreads();
        int excl = incl - x + (w ? sm8[w - 1] : 0);
        if (tid < NB) g_bbase[tid] = excl;
    }
    gbar(3);

    // phase 5: per-block tile scans -> off, cursor
    {
        int run = g_bbase[b];
        for (int t0 = cs; t0 < cs + CHUNK; t0 += BT) {
            int i = t0 + tid;
            int x = (i < ce) ? g_indeg[i] : 0;
            int incl = x;
            #pragma unroll
            for (int o = 1; o < 32; o <<= 1) {
                int n = __shfl_up_sync(0xFFFFFFFFu, incl, o);
                if (lane >= o) incl += n;
            }
            __syncthreads();
            if (lane == 31) sm8[w] = incl;
            __syncthreads();
            if (w == 0 && lane < 8) {
                int v = sm8[lane];
                #pragma unroll
                for (int o = 1; o < 8; o <<= 1) {
                    int n = __shfl_up_sync(0xFFu, v, o);
                    if (lane >= o) v += n;
                }
                sm8[lane] = v;
            }
            __syncthreads();
            int excl = incl - x + (w ? sm8[w - 1] : 0) + run;
            if (i < ce) { g_off[i] = excl; g_cursor[i] = excl; }
            run += sm8[7];
        }
        if (b == 0 && tid == 0) g_off[N_NODES] = N_EDGES;
    }
    gbar(4);

    // phase 6: place
    for (int e = gt; e < N_EDGES; e += gs) {
        int2 ed = edges[e];
        int slot = atomicAdd(&g_cursor[ed.y], 1);
        g_srcs[slot] = ed.x;
    }
}

// ---------------- aggregation: half-warp per node, float4 lanes, MLP-8 ----------------
__device__ __forceinline__ float4 agg_node4(const float* __restrict__ z,
                                            int node, int sl) {
    ulonglong2 a0 = *(const ulonglong2*)&z[node * D + sl * 4];
    unsigned long long e0 = a0.x, e1 = a0.y, o0 = 0ULL, o1 = 0ULL;
    int s0 = __ldg(&g_off[node]);
    int s1 = __ldg(&g_off[node + 1]);

    for (int j = s0; j < s1; j += 8) {
        ulonglong2 v[8];
        #pragma unroll
        for (int k = 0; k < 8; k++) {
            if (j + k < s1) {
                int a = __ldg(&g_srcs[j + k]);   // uniform within half-warp
                v[k] = *(const ulonglong2*)&z[a * D + sl * 4];
            } else {
                v[k].x = 0ULL; v[k].y = 0ULL;
            }
        }
        #pragma unroll
        for (int k = 0; k < 8; k += 2) {
            ADD_F32X2(e0, e0, v[k].x);     ADD_F32X2(e1, e1, v[k].y);
            ADD_F32X2(o0, o0, v[k + 1].x); ADD_F32X2(o1, o1, v[k + 1].y);
        }
    }
    ADD_F32X2(e0, e0, o0);
    ADD_F32X2(e1, e1, o1);
    float4 r;
    asm("mov.b64 {%0, %1}, %2;" : "=f"(r.x), "=f"(r.y) : "l"(e0));
    asm("mov.b64 {%0, %1}, %2;" : "=f"(r.z), "=f"(r.w) : "l"(e1));
    return r;
}

// ---------------- agg + bias + relu ----------------
__global__ __launch_bounds__(256)
void agg_relu_kernel(const float* __restrict__ z, float* __restrict__ h,
                     const float* __restrict__ bvec) {
    int warp = threadIdx.x >> 5;
    int lane = threadIdx.x & 31;
    int node = blockIdx.x * 16 + warp * 2 + (lane >> 4);
    int sl   = lane & 15;

    float4 acc = agg_node4(z, node, sl);
    float4 b4 = *(const float4*)&bvec[sl * 4];
    acc.x = fmaxf(acc.x + b4.x, 0.f);
    acc.y = fmaxf(acc.y + b4.y, 0.f);
    acc.z = fmaxf(acc.z + b4.z, 0.f);
    acc.w = fmaxf(acc.w + b4.w, 0.f);
    *(float4*)&h[node * D + sl * 4] = acc;
}

// ---------------- GEMM: z2 = h @ W^T (2 t-dims per thread, split-K) ----------------
#define GEMM_GRID 592
#define G_TILES (N_NODES / 8)   // 12500 tiles of 8 nodes
__global__ __launch_bounds__(128, 4)
void gemm_kernel(const float* __restrict__ in, float* __restrict__ out,
                 const float* __restrict__ W) {
    __shared__ __align__(16) float xs[8][D];
    __shared__ float ps[8][D];
    int tid = threadIdx.x;
    int t2  = tid & 31;          // output dims t2 and t2+32
    int kh  = (tid >> 5) & 1;    // K half
    int nh  = tid >> 6;          // node half (4 nodes each)

    // W rows for both t-dims, this thread's K-half, packed u64 (64 regs)
    unsigned long long wa[16], wb[16];
    const unsigned long long* Wa = (const unsigned long long*)(W + t2 * D + kh * 32);
    const unsigned long long* Wb = (const unsigned long long*)(W + (t2 + 32) * D + kh * 32);
    #pragma unroll
    for (int k = 0; k < 16; k++) { wa[k] = Wa[k]; wb[k] = Wb[k]; }

    const float4* src = (const float4*)in;
    int tile = blockIdx.x;
    float4 r0;
    if (tile < G_TILES) r0 = src[tile * 128 + tid];

    for (; tile < G_TILES; tile += GEMM_GRID) {
        ((float4*)xs)[tid] = r0;
        __syncthreads();
        int nt = tile + GEMM_GRID;
        if (nt < G_TILES) r0 = src[nt * 128 + tid];   // prefetch next tile

        unsigned long long acca[4], accb[4];
        #pragma unroll
        for (int n = 0; n < 4; n++) { acca[n] = 0ULL; accb[n] = 0ULL; }

        #pragma unroll
        for (int n = 0; n < 4; n++) {
            const ulonglong2* x = (const ulonglong2*)&xs[nh * 4 + n][kh * 32];
            #pragma unroll
            for (int dp = 0; dp < 8; dp++) {
                ulonglong2 xv = x[dp];                // LDS.128 broadcast -> 4 FFMA2
                FMA_F32X2(acca[n], xv.x, wa[2 * dp],     acca[n]);
                FMA_F32X2(accb[n], xv.x, wb[2 * dp],     accb[n]);
                FMA_F32X2(acca[n], xv.y, wa[2 * dp + 1], acca[n]);
                FMA_F32X2(accb[n], xv.y, wb[2 * dp + 1], accb[n]);
            }
        }

        float va[4], vb[4];
        #pragma unroll
        for (int n = 0; n < 4; n++) {
            float lo, hi;
            asm("mov.b64 {%0, %1}, %2;" : "=f"(lo), "=f"(hi) : "l"(acca[n]));
            va[n] = lo + hi;
            asm("mov.b64 {%0, %1}, %2;" : "=f"(lo), "=f"(hi) : "l"(accb[n]));
            vb[n] = lo + hi;
        }

        if (kh == 1) {
            #pragma unroll
            for (int n = 0; n < 4; n++) {
                ps[nh * 4 + n][t2]      = va[n];
                ps[nh * 4 + n][t2 + 32] = vb[n];
            }
        }
        __syncthreads();
        if (kh == 0) {
            int nb = tile * 8 + nh * 4;
            #pragma unroll
            for (int n = 0; n < 4; n++) {
                out[(nb + n) * D + t2]      = va[n] + ps[nh * 4 + n][t2];
                out[(nb + n) * D + t2 + 32] = vb[n] + ps[nh * 4 + n][t2 + 32];
            }
        }
        __syncthreads();
    }
}

// ---------------- fused final: agg + bias + relu + cosine ----------------
__global__ __launch_bounds__(256)
void agg_cos_kernel(const float* __restrict__ z,
                    const float* __restrict__ bvec,
                    const float* __restrict__ pattern_emb,
                    const int* __restrict__ pid,
                    float* __restrict__ out) {
    int warp = threadIdx.x >> 5;
    int lane = threadIdx.x & 31;
    int node = blockIdx.x * 16 + warp * 2 + (lane >> 4);
    int sl   = lane & 15;

    float4 acc = agg_node4(z, node, sl);
    float4 b4 = *(const float4*)&bvec[sl * 4];
    acc.x = fmaxf(acc.x + b4.x, 0.f);
    acc.y = fmaxf(acc.y + b4.y, 0.f);
    acc.z = fmaxf(acc.z + b4.z, 0.f);
    acc.w = fmaxf(acc.w + b4.w, 0.f);

    int p_id = __ldg(pid);
    float4 pv = *(const float4*)&pattern_emb[p_id * D + sl * 4];

    float num = acc.x * pv.x + acc.y * pv.y + acc.z * pv.z + acc.w * pv.w;
    float sq  = acc.x * acc.x + acc.y * acc.y + acc.z * acc.z + acc.w * acc.w;
    float psq = pv.x * pv.x + pv.y * pv.y + pv.z * pv.z + pv.w * pv.w;

    #pragma unroll
    for (int o = 8; o > 0; o >>= 1) {   // reduce within 16-lane half
        num += __shfl_xor_sync(0xFFFFFFFFu, num, o);
        sq  += __shfl_xor_sync(0xFFFFFFFFu, sq, o);
        psq += __shfl_xor_sync(0xFFFFFFFFu, psq, o);
    }
    if (sl == 0) {
        float denom = fmaxf(sqrtf(sq), EPS) * fmaxf(sqrtf(psq), EPS);
        out[node] = num / denom;
    }
}

// ---------------- launch ----------------
extern "C" void kernel_launch(void* const* d_in, const int* in_sizes, int n_in,
                              void* d_out, int out_size) {
    const int*   nodes       = (const int*)d_in[0];
    const int2*  edges       = (const int2*)d_in[1];
    const float* features    = (const float*)d_in[2];
    const float* node_emb    = (const float*)d_in[3];
    const float* feat_W      = (const float*)d_in[4];
    const float* feat_b      = (const float*)d_in[5];
    const float* conv1_W     = (const float*)d_in[6];
    const float* conv1_b     = (const float*)d_in[7];
    const float* pattern_emb = (const float*)d_in[8];
    const int*   pattern_id  = (const int*)d_in[9];
    float*       out         = (float*)d_out;

    float* z; float* h; float* z2;
    cudaGetSymbolAddress((void**)&z,  g_z);
    cudaGetSymbolAddress((void**)&h,  g_h);
    cudaGetSymbolAddress((void**)&z2, g_z2);

    // 1: CSR build + folded weights + z1 (persistent)
    csr_build_kernel<<<NB, BT>>>(edges, node_emb, feat_W, feat_b, conv1_W,
                                 nodes, features);
    // 2: layer-1 agg + relu
    agg_relu_kernel<<<N_NODES / 16, 256>>>(z, h, conv1_b);
    // 3: layer-2 linear
    gemm_kernel<<<GEMM_GRID, 128>>>(h, z2, conv1_W);
    // 4: layer-2 agg + relu + cosine
    agg_cos_kernel<<<N_NODES / 16, 256>>>(z2, conv1_b, pattern_emb, pattern_id, out);
}